// round 16
// baseline (speedup 1.0000x reference)
#include <cuda_runtime.h>
#include <math.h>
#include <stdint.h>

#define C_IN   256
#define HID    64
#define NCH2   198   // D + C_OUT
#define DBINS  118
#define C_OUTC 80
#define FH_    32
#define FW_    88
#define PIXELS 2816  // FH_*FW_
#define NR     128
#define NTH    256
#define BATCH  2
#define BNEPS  1e-5f

// ---------------- scratch (allocation-free) ----------------
__device__ float g_depth[BATCH * PIXELS * DBINS];   // (b, pix, d)
__device__ float g_feat [BATCH * PIXELS * C_OUTC];  // (b, pix, c)
__device__ float g_ang[NTH + 1];
__device__ float g_rad[NR + 1];

// ---------------- edges (double, matching np.linspace/pow then float cast) ----
__global__ void k_init_edges() {
    int i = threadIdx.x;
    if (i <= NTH) {
        double v;
        if (i == NTH) v = 1.5707963267948966;
        else          v = -1.5707963267948966 + (double)i * (3.141592653589793 / 256.0);
        g_ang[i] = (float)v;
    }
    if (i <= NR) {
        double t  = (double)i / 128.0;
        double rv = (i == NR) ? 60.0 : (1.0 + pow(t, 1.5) * 59.0);
        g_rad[i] = (float)rv;
    }
}

__global__ void k_zero(float* __restrict__ p, int n) {
    int i = blockIdx.x * blockDim.x + threadIdx.x;
    if (i < n) p[i] = 0.f;
}

// ---------------- fused MLP: conv1+BN+ReLU, conv2+BN, softmax, write depth/feat
// One block = 32 contiguous pixels, 256 threads.
__global__ __launch_bounds__(256) void k_mlp(
    const float* __restrict__ x,
    const float* __restrict__ w1, const float* __restrict__ b1,
    const float* __restrict__ gg1, const float* __restrict__ be1,
    const float* __restrict__ m1, const float* __restrict__ v1,
    const float* __restrict__ w2, const float* __restrict__ b2,
    const float* __restrict__ gg2, const float* __restrict__ be2,
    const float* __restrict__ m2, const float* __restrict__ v2)
{
    extern __shared__ float sm[];
    float* xs   = sm;              // 256*32 = 8192
    float* wbuf = xs + 8192;       // max(64*257, 198*65) = 16448
    float* h1s  = wbuf + 16448;    // 64*32 = 2048
    float* h2s  = h1s + 2048;      // 198*32 = 6336

    const int tid  = threadIdx.x;
    const int bn   = blockIdx.x / 88;
    const int base = (blockIdx.x % 88) * 32;

    // load x tile (coalesced) and w1 (padded rows, stride 257)
    const float* xg = x + (size_t)bn * C_IN * PIXELS + base;
    for (int i = tid; i < C_IN * 32; i += 256) {
        int c = i >> 5, p = i & 31;
        xs[i] = xg[(size_t)c * PIXELS + p];
    }
    for (int i = tid; i < HID * C_IN; i += 256) {
        int o = i >> 8, c = i & 255;
        wbuf[o * 257 + c] = w1[i];
    }
    __syncthreads();

    const int o = tid >> 2, g = tid & 3;
    {
        float acc[8] = {0,0,0,0,0,0,0,0};
        const float* wr = wbuf + o * 257;
        const float* xc = xs + g * 8;
        #pragma unroll 4
        for (int c = 0; c < C_IN; c++) {
            float wv = wr[c];
            float4 A = *(const float4*)(xc + c * 32);
            float4 B = *(const float4*)(xc + c * 32 + 4);
            acc[0] += wv * A.x; acc[1] += wv * A.y; acc[2] += wv * A.z; acc[3] += wv * A.w;
            acc[4] += wv * B.x; acc[5] += wv * B.y; acc[6] += wv * B.z; acc[7] += wv * B.w;
        }
        float inv = gg1[o] / sqrtf(v1[o] + BNEPS);
        float sh  = (b1[o] - m1[o]) * inv + be1[o];
        float4 R0, R1;
        R0.x = fmaxf(acc[0] * inv + sh, 0.f); R0.y = fmaxf(acc[1] * inv + sh, 0.f);
        R0.z = fmaxf(acc[2] * inv + sh, 0.f); R0.w = fmaxf(acc[3] * inv + sh, 0.f);
        R1.x = fmaxf(acc[4] * inv + sh, 0.f); R1.y = fmaxf(acc[5] * inv + sh, 0.f);
        R1.z = fmaxf(acc[6] * inv + sh, 0.f); R1.w = fmaxf(acc[7] * inv + sh, 0.f);
        *(float4*)(h1s + o * 32 + g * 8)     = R0;
        *(float4*)(h1s + o * 32 + g * 8 + 4) = R1;
    }
    __syncthreads();

    // stage 2 weights (stride 65)
    for (int i = tid; i < NCH2 * HID; i += 256) {
        int oo = i >> 6, c = i & 63;
        wbuf[oo * 65 + c] = w2[i];
    }
    __syncthreads();

    for (int pass = 0; pass < 4; pass++) {
        int o2 = pass * 64 + (tid >> 2);
        if (o2 < NCH2) {
            float acc[8] = {0,0,0,0,0,0,0,0};
            const float* wr = wbuf + o2 * 65;
            const float* hc = h1s + g * 8;
            #pragma unroll 8
            for (int c = 0; c < HID; c++) {
                float wv = wr[c];
                float4 A = *(const float4*)(hc + c * 32);
                float4 B = *(const float4*)(hc + c * 32 + 4);
                acc[0] += wv * A.x; acc[1] += wv * A.y; acc[2] += wv * A.z; acc[3] += wv * A.w;
                acc[4] += wv * B.x; acc[5] += wv * B.y; acc[6] += wv * B.z; acc[7] += wv * B.w;
            }
            float inv = gg2[o2] / sqrtf(v2[o2] + BNEPS);
            float sh  = (b2[o2] - m2[o2]) * inv + be2[o2];
            float4 R0, R1;
            R0.x = acc[0]*inv+sh; R0.y = acc[1]*inv+sh; R0.z = acc[2]*inv+sh; R0.w = acc[3]*inv+sh;
            R1.x = acc[4]*inv+sh; R1.y = acc[5]*inv+sh; R1.z = acc[6]*inv+sh; R1.w = acc[7]*inv+sh;
            *(float4*)(h2s + o2 * 32 + g * 8)     = R0;
            *(float4*)(h2s + o2 * 32 + g * 8 + 4) = R1;
        }
    }
    __syncthreads();

    // softmax over first DBINS channels, per pixel. 8 slices x 32 pixels.
    float* red  = xs;        // 256
    float* red2 = xs + 256;  // 256
    float* invs = xs + 512;  // 32
    const int p = tid & 31, sl = tid >> 5;

    float mx = -3.4e38f;
    for (int ch = sl; ch < DBINS; ch += 8) mx = fmaxf(mx, h2s[ch * 32 + p]);
    red[sl * 32 + p] = mx;
    __syncthreads();
    if (sl == 0) {
        for (int k = 1; k < 8; k++) mx = fmaxf(mx, red[k * 32 + p]);
        red2[p] = mx;
    }
    __syncthreads();
    mx = red2[p];
    float s = 0.f;
    for (int ch = sl; ch < DBINS; ch += 8) {
        float e = expf(h2s[ch * 32 + p] - mx);
        h2s[ch * 32 + p] = e;
        s += e;
    }
    __syncthreads();   // all reads of red (max partials) done; safe to overwrite
    red[sl * 32 + p] = s;
    __syncthreads();
    if (sl == 0) {
        for (int k = 1; k < 8; k++) s += red[k * 32 + p];
        invs[p] = 1.f / s;
    }
    __syncthreads();

    // write depth (pixel-major, d contiguous) and feat (pixel-major, c contiguous)
    float* dep = g_depth + (size_t)(bn * PIXELS + base) * DBINS;
    for (int i = tid; i < DBINS * 32; i += 256) {
        int pp = i / DBINS, ch = i - pp * DBINS;
        dep[(size_t)pp * DBINS + ch] = h2s[ch * 32 + pp] * invs[pp];
    }
    float* ft = g_feat + (size_t)(bn * PIXELS + base) * C_OUTC;
    for (int i = tid; i < C_OUTC * 32; i += 256) {
        int pp = i / C_OUTC, ch = i - pp * C_OUTC;
        ft[(size_t)pp * C_OUTC + ch] = h2s[(DBINS + ch) * 32 + pp];
    }
}

// ---------------- scatter: one block per (b, w) column --------------------
// g[r][h] = sum over d in r-bin of depth; then acc[r][c] = sum_h g[r][h]*feat[c][h]
// (small shared GEMM) -> atomicAdd into bev[b, c, r, t0]. Fallback per-point
// atomics for any point whose theta bin differs from the column consensus.
__global__ __launch_bounds__(256) void k_scatter(
    const float* __restrict__ rots, const float* __restrict__ trans,
    const float* __restrict__ intr, float* __restrict__ bev)
{
    extern __shared__ float sm[];
    float* re_s    = sm;            // 129 (pad to 132)
    float* ae_s    = sm + 132;      // 257 (pad to 260)
    float* depth_s = sm + 392;      // 32*121 = 3872 (pad 118->121, conflict-free)
    float* feat_s  = sm + 4264;     // 32*80 = 2560 (16B aligned)
    float* g_s     = sm + 6824;     // 32*129 = 4128 (pad 128->129)
    unsigned short* code_s = (unsigned short*)(sm + 10952); // 3776 ushorts
    int* s_t0 = (int*)(sm + 10952 + 1888);

    const int tid = threadIdx.x;
    const int b = blockIdx.x / FW_;
    const int w = blockIdx.x % FW_;

    for (int i = tid; i < NR + 1;  i += 256) re_s[i] = g_rad[i];
    for (int i = tid; i < NTH + 1; i += 256) ae_s[i] = g_ang[i];

    const float* dg = g_depth + (size_t)(b * PIXELS + w) * DBINS;
    for (int i = tid; i < FH_ * DBINS; i += 256) {
        int h = i / DBINS, d = i - h * DBINS;
        depth_s[h * 121 + d] = dg[(size_t)h * FW_ * DBINS + d];
    }
    const float* fg = g_feat + (size_t)(b * PIXELS + w) * C_OUTC;
    for (int i = tid; i < FH_ * C_OUTC; i += 256) {
        int h = i / C_OUTC, c = i - h * C_OUTC;
        feat_s[h * C_OUTC + c] = fg[(size_t)h * FW_ * C_OUTC + c];
    }
    for (int i = tid; i < 32 * 129; i += 256) g_s[i] = 0.f;

    const float fx = intr[b*9+0], cx = intr[b*9+2], fy = intr[b*9+4], cy = intr[b*9+5];
    const float r00 = rots[b*9+0], r01 = rots[b*9+1], r02 = rots[b*9+2];
    const float r10 = rots[b*9+3], r11 = rots[b*9+4], r12 = rots[b*9+5];
    const float tx = trans[b*3+0], ty = trans[b*3+1];
    const float u = (w == FW_-1) ? 703.f : (float)((double)w * (703.0 / 87.0));
    __syncthreads();

    // per-point bins (general path: depends on d AND h)
    for (int i = tid; i < DBINS * FH_; i += 256) {
        int d = i >> 5, h = i & 31;
        float dd = 1.0f + 0.5f * (float)d;
        float v  = (h == FH_-1) ? 255.f : (float)((double)h * (255.0 / 31.0));
        float X = (u - cx) * dd / fx;
        float Y = (v - cy) * dd / fy;
        float Z = dd;
        float px = r00 * X + r01 * Y + r02 * Z + tx;
        float py = r10 * X + r11 * Y + r12 * Z + ty;
        float rr = sqrtf(px * px + py * py);
        float th = atan2f(py, px);
        int lo = 0, hi = NR + 1;
        while (lo < hi) { int mid = (lo + hi) >> 1; if (re_s[mid] <= rr) lo = mid + 1; else hi = mid; }
        int ri = lo - 1;
        lo = 0; hi = NTH + 1;
        while (lo < hi) { int mid = (lo + hi) >> 1; if (ae_s[mid] <= th) lo = mid + 1; else hi = mid; }
        int ti = lo - 1;
        unsigned short code = 0xFFFFu;
        if (ri >= 0 && ri < NR && ti >= 0 && ti < NTH)
            code = (unsigned short)((ri << 8) | ti);
        code_s[i] = code;
    }
    __syncthreads();

    if (tid == 0) {
        int t0 = -1;
        for (int i = 0; i < DBINS * FH_; i++)
            if (code_s[i] != 0xFFFFu) { t0 = (int)(code_s[i] & 255); break; }
        *s_t0 = t0;
    }
    __syncthreads();
    const int t0 = *s_t0;

    // g accumulation: thread-per-h, serial over d (race-free)
    if (tid < 32 && t0 >= 0) {
        int h = tid;
        for (int d = 0; d < DBINS; d++) {
            unsigned short code = code_s[d * 32 + h];
            if (code != 0xFFFFu) {
                int ti = code & 255, ri = code >> 8;
                float dv = depth_s[h * 121 + d];
                if (ti == t0) {
                    g_s[h * 129 + ri] += dv;
                } else {
                    // rare general-case fallback: direct scatter of this point
                    float* op = bev + ((size_t)(b * C_OUTC) * NR + ri) * NTH + ti;
                    for (int c = 0; c < C_OUTC; c++)
                        atomicAdd(op + (size_t)c * (NR * NTH), dv * feat_s[h * C_OUTC + c]);
                }
            }
        }
    }
    __syncthreads();
    if (t0 < 0) return;

    // column GEMM: acc[r][c] = sum_h g[r][h] * feat[h][c], then atomic out
    const int r = tid & 127, half = tid >> 7;
    bool act = false;
    for (int h = 0; h < FH_; h++) if (g_s[h * 129 + r] != 0.f) { act = true; break; }
    if (!act) return;

    for (int k = 0; k < 5; k++) {
        int cb = half * 40 + k * 8;
        float acc[8] = {0,0,0,0,0,0,0,0};
        #pragma unroll
        for (int h = 0; h < FH_; h++) {
            float gv = g_s[h * 129 + r];
            float4 A = *(const float4*)(feat_s + h * C_OUTC + cb);
            float4 B = *(const float4*)(feat_s + h * C_OUTC + cb + 4);
            acc[0] += gv * A.x; acc[1] += gv * A.y; acc[2] += gv * A.z; acc[3] += gv * A.w;
            acc[4] += gv * B.x; acc[5] += gv * B.y; acc[6] += gv * B.z; acc[7] += gv * B.w;
        }
        size_t obase = ((size_t)(b * C_OUTC + cb) * NR + r) * NTH + (size_t)t0;
        #pragma unroll
        for (int j = 0; j < 8; j++)
            atomicAdd(bev + obase + (size_t)j * (NR * NTH), acc[j]);
    }
}

// ---------------- launch ----------------
extern "C" void kernel_launch(void* const* d_in, const int* in_sizes, int n_in,
                              void* d_out, int out_size) {
    const float* x     = (const float*)d_in[0];
    const float* rots  = (const float*)d_in[1];
    const float* trans = (const float*)d_in[2];
    const float* intr  = (const float*)d_in[3];
    const float* w1    = (const float*)d_in[4];
    const float* b1    = (const float*)d_in[5];
    const float* gg1   = (const float*)d_in[6];
    const float* be1   = (const float*)d_in[7];
    const float* m1    = (const float*)d_in[8];
    const float* v1    = (const float*)d_in[9];
    const float* w2    = (const float*)d_in[10];
    const float* b2    = (const float*)d_in[11];
    const float* gg2   = (const float*)d_in[12];
    const float* be2   = (const float*)d_in[13];
    const float* m2    = (const float*)d_in[14];
    const float* v2    = (const float*)d_in[15];
    float* bev = (float*)d_out;

    const int SMEM_MLP  = 33024 * 4;   // 132096 B
    const int SMEM_SCAT = 51456;       // B (rounded)
    cudaFuncSetAttribute(k_mlp,     cudaFuncAttributeMaxDynamicSharedMemorySize, SMEM_MLP);
    cudaFuncSetAttribute(k_scatter, cudaFuncAttributeMaxDynamicSharedMemorySize, SMEM_SCAT);

    k_init_edges<<<1, 288>>>();
    k_zero<<<(out_size + 255) / 256, 256>>>(bev, out_size);
    k_mlp<<<(BATCH * PIXELS) / 32, 256, SMEM_MLP>>>(x, w1, b1, gg1, be1, m1, v1,
                                                    w2, b2, gg2, be2, m2, v2);
    k_scatter<<<BATCH * FW_, 256, SMEM_SCAT>>>(rots, trans, intr, bev);
}

// round 17
// speedup vs baseline: 1.4756x; 1.4756x over previous
#include <cuda_runtime.h>
#include <math.h>
#include <stdint.h>

#define C_IN   256
#define HID    64
#define NCH2   198   // D + C_OUT
#define DBINS  118
#define C_OUTC 80
#define FH_    32
#define FW_    88
#define PIXELS 2816  // FH_*FW_
#define NR     128
#define NTH    256
#define BATCH  2
#define BNEPS  1e-5f

// ---------------- scratch (allocation-free) ----------------
__device__ float g_depth[BATCH * PIXELS * DBINS];   // (b, pix, d)
__device__ float g_feat [BATCH * PIXELS * C_OUTC];  // (b, pix, c)
__device__ float g_ang[NTH + 1];
__device__ float g_rad[NR + 1];

// ---------------- edges (double, matching np.linspace/pow then float cast) ----
__global__ void k_init_edges() {
    int i = threadIdx.x;
    if (i <= NTH) {
        double v;
        if (i == NTH) v = 1.5707963267948966;
        else          v = -1.5707963267948966 + (double)i * (3.141592653589793 / 256.0);
        g_ang[i] = (float)v;
    }
    if (i <= NR) {
        double t  = (double)i / 128.0;
        double rv = (i == NR) ? 60.0 : (1.0 + pow(t, 1.5) * 59.0);
        g_rad[i] = (float)rv;
    }
}

__global__ void k_zero4(float4* __restrict__ p, int n4) {
    int i = blockIdx.x * blockDim.x + threadIdx.x;
    if (i < n4) p[i] = make_float4(0.f, 0.f, 0.f, 0.f);
}

// ---------------- fused MLP: conv1+BN+ReLU, conv2+BN, softmax ----------------
// One block = 64 contiguous pixels, 256 threads, 4o x 4p register tile.
__global__ __launch_bounds__(256) void k_mlp(
    const float* __restrict__ x,
    const float* __restrict__ w1, const float* __restrict__ b1,
    const float* __restrict__ gg1, const float* __restrict__ be1,
    const float* __restrict__ m1, const float* __restrict__ v1,
    const float* __restrict__ w2, const float* __restrict__ b2,
    const float* __restrict__ gg2, const float* __restrict__ be2,
    const float* __restrict__ m2, const float* __restrict__ v2)
{
    extern __shared__ float sm[];
    float* xs   = sm;              // 16384 floats (256c x 64p)
    float* wbuf = sm + 16384;      // 16384 floats (w1: 64x256 / w2: 198x64)
    float* h1s  = sm + 32768;      // 4096 floats (64o x 64p)
    float* h2s  = xs;              // alias: xs dead after stage 1 (198x64 <= 16384)

    const int tid  = threadIdx.x;
    const int bn   = blockIdx.x / 44;
    const int base = (blockIdx.x % 44) * 64;

    // load x tile (float4 coalesced) and w1
    const float4* xg4 = (const float4*)(x + (size_t)bn * C_IN * PIXELS + base);
    for (int i = tid; i < 4096; i += 256) {
        int c = i >> 4, p4 = i & 15;
        ((float4*)xs)[c * 16 + p4] = xg4[c * (PIXELS / 4) + p4];
    }
    const float4* w1_4 = (const float4*)w1;
    for (int i = tid; i < 4096; i += 256) ((float4*)wbuf)[i] = w1_4[i];
    __syncthreads();

    const int og = tid >> 4;   // 0..15
    const int pg = tid & 15;   // 0..15

    // ---- stage 1: h1 = relu(bn1(w1 @ x)) ----
    {
        float acc[4][4];
        #pragma unroll
        for (int k = 0; k < 4; k++)
            #pragma unroll
            for (int j = 0; j < 4; j++) acc[k][j] = 0.f;

        const float* xc = xs + pg * 4;
        #pragma unroll 4
        for (int c = 0; c < C_IN; c++) {
            float4 X = *(const float4*)(xc + c * 64);
            #pragma unroll
            for (int k = 0; k < 4; k++) {
                float wv = wbuf[(og + 16 * k) * 256 + c];
                acc[k][0] += wv * X.x; acc[k][1] += wv * X.y;
                acc[k][2] += wv * X.z; acc[k][3] += wv * X.w;
            }
        }
        #pragma unroll
        for (int k = 0; k < 4; k++) {
            int o = og + 16 * k;
            float inv = gg1[o] / sqrtf(v1[o] + BNEPS);
            float sh  = (b1[o] - m1[o]) * inv + be1[o];
            float4 R;
            R.x = fmaxf(acc[k][0] * inv + sh, 0.f);
            R.y = fmaxf(acc[k][1] * inv + sh, 0.f);
            R.z = fmaxf(acc[k][2] * inv + sh, 0.f);
            R.w = fmaxf(acc[k][3] * inv + sh, 0.f);
            *(float4*)(h1s + o * 64 + pg * 4) = R;
        }
    }
    __syncthreads();

    // ---- stage 2 weights ----
    const float4* w2_4 = (const float4*)w2;
    for (int i = tid; i < 3168; i += 256) ((float4*)wbuf)[i] = w2_4[i];
    __syncthreads();

    // ---- stage 2: h2 = bn2(w2 @ h1), 4 passes of 64 outputs ----
    #pragma unroll
    for (int pass = 0; pass < 4; pass++) {
        float acc[4][4];
        #pragma unroll
        for (int k = 0; k < 4; k++)
            #pragma unroll
            for (int j = 0; j < 4; j++) acc[k][j] = 0.f;

        const float* hc = h1s + pg * 4;
        #pragma unroll 4
        for (int c = 0; c < HID; c++) {
            float4 X = *(const float4*)(hc + c * 64);
            #pragma unroll
            for (int k = 0; k < 4; k++) {
                // unguarded read: o*64+c < 16384 always; stale-but-finite values,
                // results guarded at write
                float wv = wbuf[(pass * 64 + og + 16 * k) * 64 + c];
                acc[k][0] += wv * X.x; acc[k][1] += wv * X.y;
                acc[k][2] += wv * X.z; acc[k][3] += wv * X.w;
            }
        }
        #pragma unroll
        for (int k = 0; k < 4; k++) {
            int o = pass * 64 + og + 16 * k;
            if (o < NCH2) {
                float inv = gg2[o] / sqrtf(v2[o] + BNEPS);
                float sh  = (b2[o] - m2[o]) * inv + be2[o];
                float4 R;
                R.x = acc[k][0] * inv + sh; R.y = acc[k][1] * inv + sh;
                R.z = acc[k][2] * inv + sh; R.w = acc[k][3] * inv + sh;
                *(float4*)(h2s + o * 64 + pg * 4) = R;
            }
        }
    }
    __syncthreads();

    // ---- softmax over first DBINS channels per pixel (4 slices x 64 pixels) ----
    float* red  = wbuf;        // 256
    float* invs = wbuf + 256;  // 64
    const int p = tid & 63, sl = tid >> 6;

    float mx = -3.4e38f;
    for (int ch = sl; ch < DBINS; ch += 4) mx = fmaxf(mx, h2s[ch * 64 + p]);
    red[sl * 64 + p] = mx;
    __syncthreads();
    if (sl == 0) {
        for (int k = 1; k < 4; k++) mx = fmaxf(mx, red[k * 64 + p]);
        red[p] = mx;
    }
    __syncthreads();
    mx = red[p];
    float s = 0.f;
    for (int ch = sl; ch < DBINS; ch += 4) {
        float e = expf(h2s[ch * 64 + p] - mx);
        h2s[ch * 64 + p] = e;
        s += e;
    }
    __syncthreads();
    red[sl * 64 + p] = s;
    __syncthreads();
    if (sl == 0) {
        for (int k = 1; k < 4; k++) s += red[k * 64 + p];
        invs[p] = 1.f / s;
    }
    __syncthreads();

    // ---- write depth (pix-major, d contiguous) and feat (pix-major, c contiguous)
    float* dep = g_depth + (size_t)(bn * PIXELS + base) * DBINS;
    for (int i = tid; i < DBINS * 64; i += 256) {
        int pp = i / DBINS, ch = i - pp * DBINS;
        dep[(size_t)pp * DBINS + ch] = h2s[ch * 64 + pp] * invs[pp];
    }
    float* ft = g_feat + (size_t)(bn * PIXELS + base) * C_OUTC;
    for (int i = tid; i < C_OUTC * 64; i += 256) {
        int pp = i / C_OUTC, ch = i - pp * C_OUTC;
        ft[(size_t)pp * C_OUTC + ch] = h2s[(DBINS + ch) * 64 + pp];
    }
}

// ---------------- scatter: one block per (b, w) column --------------------
__global__ __launch_bounds__(256) void k_scatter(
    const float* __restrict__ rots, const float* __restrict__ trans,
    const float* __restrict__ intr, float* __restrict__ bev)
{
    extern __shared__ float sm[];
    float* re_s    = sm;            // 129 (pad to 132)
    float* ae_s    = sm + 132;      // 257 (pad to 260)
    float* depth_s = sm + 392;      // 32*121 = 3872
    float* feat_s  = sm + 4264;     // 32*80 = 2560
    float* g_s     = sm + 6824;     // 32*129 = 4128
    unsigned short* code_s = (unsigned short*)(sm + 10952); // 3776 ushorts
    int* s_t0 = (int*)(sm + 12840);

    const int tid = threadIdx.x;
    const int b = blockIdx.x / FW_;
    const int w = blockIdx.x % FW_;

    for (int i = tid; i < NR + 1;  i += 256) re_s[i] = g_rad[i];
    for (int i = tid; i < NTH + 1; i += 256) ae_s[i] = g_ang[i];

    const float* dg = g_depth + (size_t)(b * PIXELS + w) * DBINS;
    for (int i = tid; i < FH_ * DBINS; i += 256) {
        int h = i / DBINS, d = i - h * DBINS;
        depth_s[h * 121 + d] = dg[(size_t)h * FW_ * DBINS + d];
    }
    const float* fg = g_feat + (size_t)(b * PIXELS + w) * C_OUTC;
    for (int i = tid; i < FH_ * C_OUTC; i += 256) {
        int h = i / C_OUTC, c = i - h * C_OUTC;
        feat_s[h * C_OUTC + c] = fg[(size_t)h * FW_ * C_OUTC + c];
    }
    for (int i = tid; i < 32 * 129; i += 256) g_s[i] = 0.f;
    if (tid == 0) *s_t0 = 0x7fffffff;

    const float fx = intr[b*9+0], cx = intr[b*9+2], fy = intr[b*9+4], cy = intr[b*9+5];
    const float r00 = rots[b*9+0], r01 = rots[b*9+1], r02 = rots[b*9+2];
    const float r10 = rots[b*9+3], r11 = rots[b*9+4], r12 = rots[b*9+5];
    const float tx = trans[b*3+0], ty = trans[b*3+1];
    const float u = (w == FW_-1) ? 703.f : (float)((double)w * (703.0 / 87.0));
    __syncthreads();

    // per-point bins + parallel consensus (min valid theta bin)
    for (int i = tid; i < DBINS * FH_; i += 256) {
        int d = i >> 5, h = i & 31;
        float dd = 1.0f + 0.5f * (float)d;
        float v  = (h == FH_-1) ? 255.f : (float)((double)h * (255.0 / 31.0));
        float X = (u - cx) * dd / fx;
        float Y = (v - cy) * dd / fy;
        float Z = dd;
        float px = r00 * X + r01 * Y + r02 * Z + tx;
        float py = r10 * X + r11 * Y + r12 * Z + ty;
        float rr = sqrtf(px * px + py * py);
        float th = atan2f(py, px);
        int lo = 0, hi = NR + 1;
        while (lo < hi) { int mid = (lo + hi) >> 1; if (re_s[mid] <= rr) lo = mid + 1; else hi = mid; }
        int ri = lo - 1;
        lo = 0; hi = NTH + 1;
        while (lo < hi) { int mid = (lo + hi) >> 1; if (ae_s[mid] <= th) lo = mid + 1; else hi = mid; }
        int ti = lo - 1;
        unsigned short code = 0xFFFFu;
        if (ri >= 0 && ri < NR && ti >= 0 && ti < NTH) {
            code = (unsigned short)((ri << 8) | ti);
            atomicMin(s_t0, ti);
        }
        code_s[i] = code;
    }
    __syncthreads();
    int t0 = *s_t0;
    if (t0 == 0x7fffffff) t0 = -1;

    // parallel g accumulation via shared atomics (addresses bank-spread: 129 % 32 == 1)
    if (t0 >= 0) {
        for (int i = tid; i < DBINS * FH_; i += 256) {
            unsigned short code = code_s[i];
            if (code != 0xFFFFu) {
                int d = i >> 5, h = i & 31;
                int ti = code & 255, ri = code >> 8;
                float dv = depth_s[h * 121 + d];
                if (ti == t0) {
                    atomicAdd(&g_s[h * 129 + ri], dv);
                } else {
                    // rare general-case fallback: direct scatter of this point
                    float* op = bev + ((size_t)(b * C_OUTC) * NR + ri) * NTH + ti;
                    for (int c = 0; c < C_OUTC; c++)
                        atomicAdd(op + (size_t)c * (NR * NTH), dv * feat_s[h * C_OUTC + c]);
                }
            }
        }
    }
    __syncthreads();
    if (t0 < 0) return;

    // column GEMM: acc[r][c] = sum_h g[r][h] * feat[h][c], then atomic out
    const int r = tid & 127, half = tid >> 7;
    bool act = false;
    for (int h = 0; h < FH_; h++) if (g_s[h * 129 + r] != 0.f) { act = true; break; }
    if (!act) return;

    for (int k = 0; k < 5; k++) {
        int cb = half * 40 + k * 8;
        float acc[8] = {0,0,0,0,0,0,0,0};
        #pragma unroll
        for (int h = 0; h < FH_; h++) {
            float gv = g_s[h * 129 + r];
            float4 A = *(const float4*)(feat_s + h * C_OUTC + cb);
            float4 B = *(const float4*)(feat_s + h * C_OUTC + cb + 4);
            acc[0] += gv * A.x; acc[1] += gv * A.y; acc[2] += gv * A.z; acc[3] += gv * A.w;
            acc[4] += gv * B.x; acc[5] += gv * B.y; acc[6] += gv * B.z; acc[7] += gv * B.w;
        }
        size_t obase = ((size_t)(b * C_OUTC + cb) * NR + r) * NTH + (size_t)t0;
        #pragma unroll
        for (int j = 0; j < 8; j++)
            atomicAdd(bev + obase + (size_t)j * (NR * NTH), acc[j]);
    }
}

// ---------------- launch ----------------
extern "C" void kernel_launch(void* const* d_in, const int* in_sizes, int n_in,
                              void* d_out, int out_size) {
    const float* x     = (const float*)d_in[0];
    const float* rots  = (const float*)d_in[1];
    const float* trans = (const float*)d_in[2];
    const float* intr  = (const float*)d_in[3];
    const float* w1    = (const float*)d_in[4];
    const float* b1    = (const float*)d_in[5];
    const float* gg1   = (const float*)d_in[6];
    const float* be1   = (const float*)d_in[7];
    const float* m1    = (const float*)d_in[8];
    const float* v1    = (const float*)d_in[9];
    const float* w2    = (const float*)d_in[10];
    const float* b2    = (const float*)d_in[11];
    const float* gg2   = (const float*)d_in[12];
    const float* be2   = (const float*)d_in[13];
    const float* m2    = (const float*)d_in[14];
    const float* v2    = (const float*)d_in[15];
    float* bev = (float*)d_out;

    const int SMEM_MLP  = 36864 * 4;   // 147456 B
    const int SMEM_SCAT = 51456;       // B
    cudaFuncSetAttribute(k_mlp,     cudaFuncAttributeMaxDynamicSharedMemorySize, SMEM_MLP);
    cudaFuncSetAttribute(k_scatter, cudaFuncAttributeMaxDynamicSharedMemorySize, SMEM_SCAT);

    k_init_edges<<<1, 288>>>();
    int n4 = out_size / 4;
    k_zero4<<<(n4 + 255) / 256, 256>>>((float4*)bev, n4);
    k_mlp<<<(BATCH * PIXELS) / 64, 256, SMEM_MLP>>>(x, w1, b1, gg1, be1, m1, v1,
                                                    w2, b2, gg2, be2, m2, v2);
    k_scatter<<<BATCH * FW_, 256, SMEM_SCAT>>>(rots, trans, intr, bev);
}